// round 15
// baseline (speedup 1.0000x reference)
#include <cuda_runtime.h>
#include <math.h>

#define NPTS 1024
#define TLEN 64
#define CDIM 256
#define NTILE 32                         // 1024 / 32
#define NBLK (NTILE * (NTILE + 1) / 2)   // 528 triangular tiles

typedef unsigned int uint32;

// Scratch (__device__ globals — no allocation allowed).
__device__ uint32 g_xtf[2][NPTS * CDIM]; // time-means pre-converted to tf32 bits
__device__ float  g_norm[2][NPTS];       // row squared norms (fp32 exact)
__device__ float  g_rs[2][NPTS];         // row sums of d (atomic-accumulated)
__device__ double g_acc[3];              // sum(dx*dy), sum(dx*dx), sum(dy*dy)
__device__ unsigned int g_ticket;        // last-block-done counter

__device__ __forceinline__ uint32 f2tf(float v) {
    uint32 r;
    asm("cvt.rna.tf32.f32 %0, %1;" : "=r"(r) : "f"(v));
    return r;
}
__device__ __forceinline__ void mma_tf32(float* c,
                                         uint32 a0, uint32 a1, uint32 a2, uint32 a3,
                                         uint32 b0, uint32 b1) {
    asm("mma.sync.aligned.m16n8k8.row.col.f32.tf32.tf32.f32 "
        "{%0,%1,%2,%3},{%4,%5,%6,%7},{%8,%9},{%0,%1,%2,%3};"
        : "+f"(c[0]), "+f"(c[1]), "+f"(c[2]), "+f"(c[3])
        : "r"(a0), "r"(a1), "r"(a2), "r"(a3), "r"(b0), "r"(b1));
}

// ---------------------------------------------------------------------------
// Kernel 1: time-mean over T + per-row squared norm + tf32 pre-conversion.
// (proven: HBM-ceiling bound, ~24.5us) grid (512, 2), block 256.
// ---------------------------------------------------------------------------
__global__ void mean_norm_kernel(const float* __restrict__ a,
                                 const float* __restrict__ b) {
    const int w = blockIdx.y;
    const float* __restrict__ src = (w == 0) ? a : b;
    const int tid  = threadIdx.x;
    const int row  = tid >> 7;
    const int half = (tid >> 6) & 1;
    const int c4   = tid & 63;
    const int n    = blockIdx.x * 2 + row;

    if (blockIdx.x == 0) {   // fold init
#pragma unroll
        for (int r = 0; r < 4; ++r) g_rs[w][tid + 256 * r] = 0.f;
        if (w == 0 && tid == 0) {
            g_acc[0] = 0.0; g_acc[1] = 0.0; g_acc[2] = 0.0;
            g_ticket = 0u;
        }
    }

    const float4* __restrict__ p =
        (const float4*)(src + (size_t)n * (TLEN * CDIM)) + half * 32 * (CDIM / 4) + c4;
    float4 s0 = make_float4(0.f, 0.f, 0.f, 0.f);
    float4 s1 = make_float4(0.f, 0.f, 0.f, 0.f);
#pragma unroll
    for (int t = 0; t < 16; ++t) {
        float4 v0 = __ldcs(p + (size_t)(2 * t) * (CDIM / 4));
        float4 v1 = __ldcs(p + (size_t)(2 * t + 1) * (CDIM / 4));
        s0.x += v0.x; s0.y += v0.y; s0.z += v0.z; s0.w += v0.w;
        s1.x += v1.x; s1.y += v1.y; s1.z += v1.z; s1.w += v1.w;
    }
    float4 s;
    s.x = s0.x + s1.x; s.y = s0.y + s1.y; s.z = s0.z + s1.z; s.w = s0.w + s1.w;

    __shared__ float4 sh[2][2][64];
    __shared__ float part[2][2];
    sh[row][half][c4] = s;
    __syncthreads();

    if (half == 0) {
        const float4 o = sh[row][1][c4];
        const float inv = 1.0f / TLEN;
        float4 m;
        m.x = (s.x + o.x) * inv; m.y = (s.y + o.y) * inv;
        m.z = (s.z + o.z) * inv; m.w = (s.w + o.w) * inv;

        uint4 u;
        u.x = f2tf(m.x); u.y = f2tf(m.y); u.z = f2tf(m.z); u.w = f2tf(m.w);
        ((uint4*)(g_xtf[w] + (size_t)n * CDIM))[c4] = u;

        float sq = m.x * m.x + m.y * m.y + m.z * m.z + m.w * m.w;
#pragma unroll
        for (int off = 16; off > 0; off >>= 1)
            sq += __shfl_down_sync(0xffffffffu, sq, off);
        if ((c4 & 31) == 0) part[row][c4 >> 5] = sq;
    }
    __syncthreads();
    if ((tid & 127) == 0) g_norm[w][n] = part[row][0] + part[row][1];
}

// ---------------------------------------------------------------------------
// Kernel 2: triangular tf32-mma pairwise-distance GEMM, 32x32 tiles.
// 528 blocks (3-4 co-resident per SM), 128 threads, 4 warps:
//   warps 0-1: x-matrix (rows 16*wsub..+15, all 32 cols)
//   warps 2-3: y-matrix, same positions (1:1 smem exchange for pxy)
// Fused stats + ticket finalize.
// ---------------------------------------------------------------------------
__global__ void __launch_bounds__(128) gemm_mma_kernel(float* __restrict__ out) {
    const int tb = blockIdx.x;
    int by = (int)((__fsqrt_rn(8.f * (float)tb + 1.f) - 1.f) * 0.5f);
    while ((by + 1) * (by + 2) / 2 <= tb) ++by;
    while (by * (by + 1) / 2 > tb) --by;
    const int bx = tb - by * (by + 1) / 2;
    const bool diag = (bx == by);
    const int I = bx * 32;   // rows
    const int J = by * 32;   // cols

    __shared__ uint32 sA[2][32][36];   // [mat][m][k] tf32 bits (I-rows)
    __shared__ uint32 sB[2][32][36];   // [mat][n][k] tf32 bits (J-rows)
    __shared__ float sh_rs[2][32], sh_cs[2][32];
    __shared__ float sh_p[3][2];
    __shared__ unsigned int s_last;

    float* gyv = (float*)&sA[0][0][0]; // overlay after mainloop: 32*33 floats

    const int tid  = threadIdx.x;          // 0..127
    const int warp = tid >> 5, lane = tid & 31;
    const int mat  = warp >> 1;            // 0: x, 1: y
    const int wsub = warp & 1;             // row half
    const int g = lane >> 2, tig = lane & 3;

    if (tid < 64) {
        const int w2 = tid >> 5;
        sh_cs[w2][tid & 31] = 0.f;
    }

    float cc[4][4];                        // [t][q], warp tile 16x32
#pragma unroll
    for (int t = 0; t < 4; ++t)
#pragma unroll
        for (int q = 0; q < 4; ++q) cc[t][q] = 0.f;

    // fill mapping: m = tid>>2 (0..31), kq = (tid&3)*8 : 8 uint32 (2 uint4)
    const int m  = tid >> 2;
    const int kq = (tid & 3) * 8;

    uint4 fA[2][2], fB[2][2];
#pragma unroll
    for (int w = 0; w < 2; ++w)
#pragma unroll
        for (int q = 0; q < 2; ++q) {
            fA[w][q] = *(const uint4*)(g_xtf[w] + (size_t)(I + m) * CDIM + kq + 4 * q);
            fB[w][q] = *(const uint4*)(g_xtf[w] + (size_t)(J + m) * CDIM + kq + 4 * q);
        }

    const int r0 = 16 * wsub + g;          // this warp's A row base

    for (int c = 0; c < 8; ++c) {
        __syncthreads();
#pragma unroll
        for (int w = 0; w < 2; ++w)
#pragma unroll
            for (int q = 0; q < 2; ++q) {
                *(uint4*)&sA[w][m][kq + 4 * q] = fA[w][q];
                *(uint4*)&sB[w][m][kq + 4 * q] = fB[w][q];
            }
        __syncthreads();
        if (c < 7) {
            const int k0 = (c + 1) * 32;
#pragma unroll
            for (int w = 0; w < 2; ++w)
#pragma unroll
                for (int q = 0; q < 2; ++q) {
                    fA[w][q] = *(const uint4*)(g_xtf[w] + (size_t)(I + m) * CDIM + k0 + kq + 4 * q);
                    fB[w][q] = *(const uint4*)(g_xtf[w] + (size_t)(J + m) * CDIM + k0 + kq + 4 * q);
                }
        }
#pragma unroll
        for (int kk = 0; kk < 4; ++kk) {
            const int kb = kk * 8;
            const uint32 a0 = sA[mat][r0][kb + tig];
            const uint32 a1 = sA[mat][r0 + 8][kb + tig];
            const uint32 a2 = sA[mat][r0][kb + tig + 4];
            const uint32 a3 = sA[mat][r0 + 8][kb + tig + 4];
#pragma unroll
            for (int t = 0; t < 4; ++t) {
                const int nr = 8 * t + g;
                const uint32 b0 = sB[mat][nr][kb + tig];
                const uint32 b1 = sB[mat][nr][kb + tig + 4];
                mma_tf32(cc[t], a0, a1, a2, a3, b0, b1);
            }
        }
    }

    __syncthreads();   // mainloop done; sA dead -> gyv overlay safe

    // -------- distances for own matrix (diag override) --------
    const int gr0 = I + r0, gr1 = gr0 + 8;
    const float nI0 = g_norm[mat][gr0], nI1 = g_norm[mat][gr1];

    float dv[4][4];
    float pss = 0.f;                        // pxx (x-warps) / pyy (y-warps)
#pragma unroll
    for (int t = 0; t < 4; ++t) {
        const int colL = 8 * t + 2 * tig;
        const int gcA = J + colL, gcB = gcA + 1;
        const float nJA = g_norm[mat][gcA], nJB = g_norm[mat][gcB];
        float d00 = sqrtf(fmaxf(nI0 + nJA - 2.f * cc[t][0], 0.f) + 1e-12f);
        float d01 = sqrtf(fmaxf(nI0 + nJB - 2.f * cc[t][1], 0.f) + 1e-12f);
        float d10 = sqrtf(fmaxf(nI1 + nJA - 2.f * cc[t][2], 0.f) + 1e-12f);
        float d11 = sqrtf(fmaxf(nI1 + nJB - 2.f * cc[t][3], 0.f) + 1e-12f);
        if (gr0 == gcA) d00 = 1e-6f;
        if (gr0 == gcB) d01 = 1e-6f;
        if (gr1 == gcA) d10 = 1e-6f;
        if (gr1 == gcB) d11 = 1e-6f;
        dv[t][0] = d00; dv[t][1] = d01; dv[t][2] = d10; dv[t][3] = d11;
        pss += d00 * d00 + d01 * d01 + d10 * d10 + d11 * d11;
    }

    // row sums: single writer per row (warp covers all 32 cols)
    {
        float pr0 = 0.f, pr1 = 0.f;
#pragma unroll
        for (int t = 0; t < 4; ++t) {
            pr0 += dv[t][0] + dv[t][1];
            pr1 += dv[t][2] + dv[t][3];
        }
        pr0 += __shfl_down_sync(0xffffffffu, pr0, 2, 4);
        pr0 += __shfl_down_sync(0xffffffffu, pr0, 1, 4);
        pr1 += __shfl_down_sync(0xffffffffu, pr1, 2, 4);
        pr1 += __shfl_down_sync(0xffffffffu, pr1, 1, 4);
        if (tig == 0) {
            sh_rs[mat][r0]     = pr0;
            sh_rs[mat][r0 + 8] = pr1;
        }
    }
    // col sums: two wsub warps share columns -> smem atomics
#pragma unroll
    for (int t = 0; t < 4; ++t) {
        const int colL = 8 * t + 2 * tig;
        float vA = dv[t][0] + dv[t][2];
        float vB = dv[t][1] + dv[t][3];
#pragma unroll
        for (int s = 16; s >= 4; s >>= 1) {
            vA += __shfl_down_sync(0xffffffffu, vA, s);
            vB += __shfl_down_sync(0xffffffffu, vB, s);
        }
        if (g == 0) {
            atomicAdd(&sh_cs[mat][colL],     vA);
            atomicAdd(&sh_cs[mat][colL + 1], vB);
        }
    }

    // y-warps stage distances for the x-warps' cross product
    if (mat == 1) {
#pragma unroll
        for (int t = 0; t < 4; ++t) {
            const int colL = 8 * t + 2 * tig;
            gyv[r0 * 33 + colL]           = dv[t][0];
            gyv[r0 * 33 + colL + 1]       = dv[t][1];
            gyv[(r0 + 8) * 33 + colL]     = dv[t][2];
            gyv[(r0 + 8) * 33 + colL + 1] = dv[t][3];
        }
        float pyy = pss;
#pragma unroll
        for (int off = 16; off > 0; off >>= 1)
            pyy += __shfl_down_sync(0xffffffffu, pyy, off);
        if (lane == 0) sh_p[2][wsub] = pyy;
    }
    __syncthreads();   // gyv + y-stats visible

    if (mat == 0) {
        float pxy = 0.f;
#pragma unroll
        for (int t = 0; t < 4; ++t) {
            const int colL = 8 * t + 2 * tig;
            pxy += dv[t][0] * gyv[r0 * 33 + colL];
            pxy += dv[t][1] * gyv[r0 * 33 + colL + 1];
            pxy += dv[t][2] * gyv[(r0 + 8) * 33 + colL];
            pxy += dv[t][3] * gyv[(r0 + 8) * 33 + colL + 1];
        }
        float pxx = pss;
#pragma unroll
        for (int off = 16; off > 0; off >>= 1) {
            pxy += __shfl_down_sync(0xffffffffu, pxy, off);
            pxx += __shfl_down_sync(0xffffffffu, pxx, off);
        }
        if (lane == 0) { sh_p[0][wsub] = pxy; sh_p[1][wsub] = pxx; }
    }
    __syncthreads();

    if (tid < 64) {
        const int w2 = tid >> 5, r = tid & 31;
        atomicAdd(&g_rs[w2][I + r], sh_rs[w2][r]);
        if (!diag) atomicAdd(&g_rs[w2][J + r], sh_cs[w2][r]);
    }
    if (tid == 0) {
        const double scl = diag ? 1.0 : 2.0;
        atomicAdd(&g_acc[0], scl * (double)(sh_p[0][0] + sh_p[0][1]));
        atomicAdd(&g_acc[1], scl * (double)(sh_p[1][0] + sh_p[1][1]));
        atomicAdd(&g_acc[2], scl * (double)(sh_p[2][0] + sh_p[2][1]));
    }

    // -------- last-block finalize (threadfence + ticket) --------
    __threadfence();
    __syncthreads();
    if (tid == 0) s_last = (atomicAdd(&g_ticket, 1u) == NBLK - 1) ? 1u : 0u;
    __syncthreads();
    if (s_last == 0u) return;
    __threadfence();

    double sRR = 0.0, sXX = 0.0, sYY = 0.0, sX = 0.0, sY = 0.0;
#pragma unroll
    for (int q = 0; q < 8; ++q) {
        const int i = tid + q * 128;
        const double rx = (double)g_rs[0][i];
        const double ry = (double)g_rs[1][i];
        sRR += rx * ry; sXX += rx * rx; sYY += ry * ry; sX += rx; sY += ry;
    }
#pragma unroll
    for (int off = 16; off > 0; off >>= 1) {
        sRR += __shfl_down_sync(0xffffffffu, sRR, off);
        sXX += __shfl_down_sync(0xffffffffu, sXX, off);
        sYY += __shfl_down_sync(0xffffffffu, sYY, off);
        sX  += __shfl_down_sync(0xffffffffu, sX, off);
        sY  += __shfl_down_sync(0xffffffffu, sY, off);
    }
    __shared__ double sd[5][4];
    if (lane == 0) { sd[0][warp] = sRR; sd[1][warp] = sXX; sd[2][warp] = sYY; sd[3][warp] = sX; sd[4][warp] = sY; }
    __syncthreads();
    if (tid == 0) {
        double a0 = 0, a1 = 0, a2 = 0, a3 = 0, a4 = 0;
#pragma unroll
        for (int q = 0; q < 4; ++q) {
            a0 += sd[0][q]; a1 += sd[1][q]; a2 += sd[2][q]; a3 += sd[3][q]; a4 += sd[4][q];
        }
        const double N = (double)NPTS, N2 = N * N;
        const double sumab = g_acc[0] - (2.0 / N) * a0 + (a3 * a4) / N2;
        const double sumaa = g_acc[1] - (2.0 / N) * a1 + (a3 * a3) / N2;
        const double sumbb = g_acc[2] - (2.0 / N) * a2 + (a4 * a4) / N2;
        const double mxy = sumab / N2, mxx = sumaa / N2, myy = sumbb / N2;
        const double r = mxy / sqrt(mxx * myy + 1e-9);
        out[0] = (float)(1.0 - r);
    }
}

extern "C" void kernel_launch(void* const* d_in, const int* in_sizes, int n_in,
                              void* d_out, int out_size) {
    const float* a = (const float*)d_in[0];  // output_1 (1024,64,256) f32
    const float* b = (const float*)d_in[1];  // feature  (1024,64,256) f32
    // d_in[2] = mask, unused by the reference module.

    mean_norm_kernel<<<dim3(NPTS / 2, 2), 256>>>(a, b);
    gemm_mma_kernel<<<NBLK, 128>>>((float*)d_out);
}

// round 17
// speedup vs baseline: 1.0437x; 1.0437x over previous
#include <cuda_runtime.h>
#include <math.h>

#define NPTS 1024
#define TLEN 64
#define CDIM 256
#define NTILE 16                         // 1024 / 64
#define NBLK (NTILE * (NTILE + 1) / 2)   // 136 triangular tiles

typedef unsigned int uint32;

// Scratch (__device__ globals — no allocation allowed).
__device__ uint32 g_xtf[2][NPTS * CDIM]; // time-means pre-converted to tf32 bits
__device__ float  g_norm[2][NPTS];       // row squared norms (fp32 exact)
__device__ float  g_rs[2][NPTS];         // row sums of d (atomic-accumulated)
__device__ double g_acc[3];              // sum(dx*dy), sum(dx*dx), sum(dy*dy)
__device__ unsigned int g_ticket;        // last-block-done counter

__device__ __forceinline__ uint32 f2tf(float v) {
    uint32 r;
    asm("cvt.rna.tf32.f32 %0, %1;" : "=r"(r) : "f"(v));
    return r;
}
__device__ __forceinline__ float fsqrt_approx(float x) {   // 1 MUFU op, no refinement
    float r;
    asm("sqrt.approx.f32 %0, %1;" : "=f"(r) : "f"(x));
    return r;
}
__device__ __forceinline__ void mma_tf32(float* c,
                                         uint32 a0, uint32 a1, uint32 a2, uint32 a3,
                                         uint32 b0, uint32 b1) {
    asm("mma.sync.aligned.m16n8k8.row.col.f32.tf32.tf32.f32 "
        "{%0,%1,%2,%3},{%4,%5,%6,%7},{%8,%9},{%0,%1,%2,%3};"
        : "+f"(c[0]), "+f"(c[1]), "+f"(c[2]), "+f"(c[3])
        : "r"(a0), "r"(a1), "r"(a2), "r"(a3), "r"(b0), "r"(b1));
}

// ---------------------------------------------------------------------------
// Kernel 1: time-mean over T + per-row squared norm + tf32 pre-conversion.
// (proven: HBM-ceiling bound, ~24.5us) grid (512, 2), block 256.
// ---------------------------------------------------------------------------
__global__ void mean_norm_kernel(const float* __restrict__ a,
                                 const float* __restrict__ b) {
    const int w = blockIdx.y;
    const float* __restrict__ src = (w == 0) ? a : b;
    const int tid  = threadIdx.x;
    const int row  = tid >> 7;
    const int half = (tid >> 6) & 1;
    const int c4   = tid & 63;
    const int n    = blockIdx.x * 2 + row;

    if (blockIdx.x == 0) {   // fold init
#pragma unroll
        for (int r = 0; r < 4; ++r) g_rs[w][tid + 256 * r] = 0.f;
        if (w == 0 && tid == 0) {
            g_acc[0] = 0.0; g_acc[1] = 0.0; g_acc[2] = 0.0;
            g_ticket = 0u;
        }
    }

    const float4* __restrict__ p =
        (const float4*)(src + (size_t)n * (TLEN * CDIM)) + half * 32 * (CDIM / 4) + c4;
    float4 s0 = make_float4(0.f, 0.f, 0.f, 0.f);
    float4 s1 = make_float4(0.f, 0.f, 0.f, 0.f);
#pragma unroll
    for (int t = 0; t < 16; ++t) {
        float4 v0 = __ldcs(p + (size_t)(2 * t) * (CDIM / 4));
        float4 v1 = __ldcs(p + (size_t)(2 * t + 1) * (CDIM / 4));
        s0.x += v0.x; s0.y += v0.y; s0.z += v0.z; s0.w += v0.w;
        s1.x += v1.x; s1.y += v1.y; s1.z += v1.z; s1.w += v1.w;
    }
    float4 s;
    s.x = s0.x + s1.x; s.y = s0.y + s1.y; s.z = s0.z + s1.z; s.w = s0.w + s1.w;

    __shared__ float4 sh[2][2][64];
    __shared__ float part[2][2];
    sh[row][half][c4] = s;
    __syncthreads();

    if (half == 0) {
        const float4 o = sh[row][1][c4];
        const float inv = 1.0f / TLEN;
        float4 m;
        m.x = (s.x + o.x) * inv; m.y = (s.y + o.y) * inv;
        m.z = (s.z + o.z) * inv; m.w = (s.w + o.w) * inv;

        uint4 u;
        u.x = f2tf(m.x); u.y = f2tf(m.y); u.z = f2tf(m.z); u.w = f2tf(m.w);
        ((uint4*)(g_xtf[w] + (size_t)n * CDIM))[c4] = u;

        float sq = m.x * m.x + m.y * m.y + m.z * m.z + m.w * m.w;
#pragma unroll
        for (int off = 16; off > 0; off >>= 1)
            sq += __shfl_down_sync(0xffffffffu, sq, off);
        if ((c4 & 31) == 0) part[row][c4 >> 5] = sq;
    }
    __syncthreads();
    if ((tid & 127) == 0) g_norm[w][n] = part[row][0] + part[row][1];
}

// ---------------------------------------------------------------------------
// Kernel 2: triangular tf32-mma pairwise-distance GEMM, 256 threads, 8 warps:
//   warps 0-3: x-matrix, 2x2 grid of 32x32 warp tiles
//   warps 4-7: y-matrix, same positions (1:1 exchange for pxy)
// Dual accumulator banks; EPILOGUE USES sqrt.approx (1 MUFU op) — the IEEE
// sqrtf expansion was the hidden MUFU-pipe floor across all prior variants.
// Fused stats + ticket finalize. grid 136 = one wave.
// ---------------------------------------------------------------------------
__global__ void __launch_bounds__(256) gemm_mma_kernel(float* __restrict__ out) {
    const int tb = blockIdx.x;
    int by = (int)((__fsqrt_rn(8.f * (float)tb + 1.f) - 1.f) * 0.5f);
    while ((by + 1) * (by + 2) / 2 <= tb) ++by;
    while (by * (by + 1) / 2 > tb) --by;
    const int bx = tb - by * (by + 1) / 2;
    const bool diag = (bx == by);
    const int I = bx * 64;   // rows
    const int J = by * 64;   // cols

    __shared__ uint32 sA[2][64][36];   // [mat][m][k] tf32 bits (I-rows)
    __shared__ uint32 sB[2][64][36];   // [mat][n][k] tf32 bits (J-rows)
    __shared__ float sh_rs[2][64], sh_cs[2][64];
    __shared__ float sh_p[3][4];
    __shared__ unsigned int s_last;

    float* gyv = (float*)&sA[0][0][0]; // overlay after mainloop: 4096 floats

    const int tid  = threadIdx.x;          // 0..255
    const int warp = tid >> 5, lane = tid & 31;
    const int mat  = warp >> 2;            // 0: x, 1: y
    const int w4   = warp & 3;
    const int wr = w4 >> 1, wc = w4 & 1;   // 2x2 grid of 32x32 warp tiles
    const int g = lane >> 2, tig = lane & 3;

    if (tid < 128) {
        const int w2 = tid >> 6;
        sh_rs[w2][tid & 63] = 0.f;
        sh_cs[w2][tid & 63] = 0.f;
    }

    float cb[2][2][4][4];                  // [bank][mi][t][q]
#pragma unroll
    for (int bk = 0; bk < 2; ++bk)
#pragma unroll
        for (int mi = 0; mi < 2; ++mi)
#pragma unroll
            for (int t = 0; t < 4; ++t)
#pragma unroll
                for (int q = 0; q < 4; ++q) cb[bk][mi][t][q] = 0.f;

    // fill mapping: m = tid>>2 (0..63), kq = (tid&3)*8 : 8 uint32 (2 uint4)
    const int m  = tid >> 2;
    const int kq = (tid & 3) * 8;

    uint4 fA[2][2], fB[2][2];
#pragma unroll
    for (int w = 0; w < 2; ++w)
#pragma unroll
        for (int q = 0; q < 2; ++q) {
            fA[w][q] = *(const uint4*)(g_xtf[w] + (size_t)(I + m) * CDIM + kq + 4 * q);
            fB[w][q] = *(const uint4*)(g_xtf[w] + (size_t)(J + m) * CDIM + kq + 4 * q);
        }

    const int rb0 = 32 * wr + g;           // mi=0 row base
    const int nb  = 32 * wc + g;           // col base (plus 8*t)

    for (int c = 0; c < 8; ++c) {
        __syncthreads();
#pragma unroll
        for (int w = 0; w < 2; ++w)
#pragma unroll
            for (int q = 0; q < 2; ++q) {
                *(uint4*)&sA[w][m][kq + 4 * q] = fA[w][q];
                *(uint4*)&sB[w][m][kq + 4 * q] = fB[w][q];
            }
        __syncthreads();
        if (c < 7) {
            const int k0 = (c + 1) * 32;
#pragma unroll
            for (int w = 0; w < 2; ++w)
#pragma unroll
                for (int q = 0; q < 2; ++q) {
                    fA[w][q] = *(const uint4*)(g_xtf[w] + (size_t)(I + m) * CDIM + k0 + kq + 4 * q);
                    fB[w][q] = *(const uint4*)(g_xtf[w] + (size_t)(J + m) * CDIM + k0 + kq + 4 * q);
                }
        }
#pragma unroll
        for (int kk = 0; kk < 4; ++kk) {
            const int kb = kk * 8;
            const int bk = kk & 1;          // accumulator bank
            uint32 av[2][4];
#pragma unroll
            for (int mi = 0; mi < 2; ++mi) {
                const int r0 = rb0 + 16 * mi, r1 = r0 + 8;
                av[mi][0] = sA[mat][r0][kb + tig];
                av[mi][1] = sA[mat][r1][kb + tig];
                av[mi][2] = sA[mat][r0][kb + tig + 4];
                av[mi][3] = sA[mat][r1][kb + tig + 4];
            }
#pragma unroll
            for (int t = 0; t < 4; ++t) {
                const int nr = nb + 8 * t;
                const uint32 b0 = sB[mat][nr][kb + tig];
                const uint32 b1 = sB[mat][nr][kb + tig + 4];
                mma_tf32(cb[bk][0][t], av[0][0], av[0][1], av[0][2], av[0][3], b0, b1);
                mma_tf32(cb[bk][1][t], av[1][0], av[1][1], av[1][2], av[1][3], b0, b1);
            }
        }
    }

    __syncthreads();   // everyone done reading sA -> gyv overlay is safe

    // fold accumulator banks
    float cc[2][4][4];
#pragma unroll
    for (int mi = 0; mi < 2; ++mi)
#pragma unroll
        for (int t = 0; t < 4; ++t)
#pragma unroll
            for (int q = 0; q < 4; ++q)
                cc[mi][t][q] = cb[0][mi][t][q] + cb[1][mi][t][q];

    // -------- distances for own matrix (diag override) --------
    float dv[2][4][4];
    float pss = 0.f;                        // pxx (x-warps) / pyy (y-warps)
#pragma unroll
    for (int mi = 0; mi < 2; ++mi) {
        const int gr0 = I + rb0 + 16 * mi, gr1 = gr0 + 8;
        const float nI0 = g_norm[mat][gr0], nI1 = g_norm[mat][gr1];
#pragma unroll
        for (int t = 0; t < 4; ++t) {
            const int colL = 32 * wc + 8 * t + 2 * tig;
            const int gcA = J + colL, gcB = gcA + 1;
            const float nJA = g_norm[mat][gcA], nJB = g_norm[mat][gcB];
            float d00 = fsqrt_approx(fmaxf(nI0 + nJA - 2.f * cc[mi][t][0], 0.f) + 1e-12f);
            float d01 = fsqrt_approx(fmaxf(nI0 + nJB - 2.f * cc[mi][t][1], 0.f) + 1e-12f);
            float d10 = fsqrt_approx(fmaxf(nI1 + nJA - 2.f * cc[mi][t][2], 0.f) + 1e-12f);
            float d11 = fsqrt_approx(fmaxf(nI1 + nJB - 2.f * cc[mi][t][3], 0.f) + 1e-12f);
            if (gr0 == gcA) d00 = 1e-6f;
            if (gr0 == gcB) d01 = 1e-6f;
            if (gr1 == gcA) d10 = 1e-6f;
            if (gr1 == gcB) d11 = 1e-6f;
            dv[mi][t][0] = d00; dv[mi][t][1] = d01;
            dv[mi][t][2] = d10; dv[mi][t][3] = d11;
            pss += d00 * d00 + d01 * d01 + d10 * d10 + d11 * d11;
        }
    }

    // own-matrix row sums / col sums (smem atomics; 2 warps share rows/cols)
#pragma unroll
    for (int mi = 0; mi < 2; ++mi) {
        float pr0 = 0.f, pr1 = 0.f;
#pragma unroll
        for (int t = 0; t < 4; ++t) {
            pr0 += dv[mi][t][0] + dv[mi][t][1];
            pr1 += dv[mi][t][2] + dv[mi][t][3];
        }
        pr0 += __shfl_down_sync(0xffffffffu, pr0, 2, 4);
        pr0 += __shfl_down_sync(0xffffffffu, pr0, 1, 4);
        pr1 += __shfl_down_sync(0xffffffffu, pr1, 2, 4);
        pr1 += __shfl_down_sync(0xffffffffu, pr1, 1, 4);
        if (tig == 0) {
            atomicAdd(&sh_rs[mat][rb0 + 16 * mi],     pr0);
            atomicAdd(&sh_rs[mat][rb0 + 16 * mi + 8], pr1);
        }
    }
#pragma unroll
    for (int t = 0; t < 4; ++t) {
        const int colL = 32 * wc + 8 * t + 2 * tig;
        float vA = dv[0][t][0] + dv[0][t][2] + dv[1][t][0] + dv[1][t][2];
        float vB = dv[0][t][1] + dv[0][t][3] + dv[1][t][1] + dv[1][t][3];
#pragma unroll
        for (int s = 16; s >= 4; s >>= 1) {
            vA += __shfl_down_sync(0xffffffffu, vA, s);
            vB += __shfl_down_sync(0xffffffffu, vB, s);
        }
        if (g == 0) {
            atomicAdd(&sh_cs[mat][colL],     vA);
            atomicAdd(&sh_cs[mat][colL + 1], vB);
        }
    }

    // y-warps stage distances for the x-warps' cross product
    if (mat == 1) {
#pragma unroll
        for (int mi = 0; mi < 2; ++mi)
#pragma unroll
            for (int t = 0; t < 4; ++t)
                *(float4*)&gyv[((((w4 * 2 + mi) * 4 + t) * 32) + lane) * 4] =
                    make_float4(dv[mi][t][0], dv[mi][t][1], dv[mi][t][2], dv[mi][t][3]);
        float pyy = pss;
#pragma unroll
        for (int off = 16; off > 0; off >>= 1)
            pyy += __shfl_down_sync(0xffffffffu, pyy, off);
        if (lane == 0) sh_p[2][w4] = pyy;
    }
    __syncthreads();   // gyv + y-stats visible

    if (mat == 0) {
        float pxy = 0.f;
#pragma unroll
        for (int mi = 0; mi < 2; ++mi)
#pragma unroll
            for (int t = 0; t < 4; ++t) {
                const float4 dy = *(const float4*)&gyv[((((w4 * 2 + mi) * 4 + t) * 32) + lane) * 4];
                pxy += dv[mi][t][0] * dy.x + dv[mi][t][1] * dy.y +
                       dv[mi][t][2] * dy.z + dv[mi][t][3] * dy.w;
            }
        float pxx = pss;
#pragma unroll
        for (int off = 16; off > 0; off >>= 1) {
            pxy += __shfl_down_sync(0xffffffffu, pxy, off);
            pxx += __shfl_down_sync(0xffffffffu, pxx, off);
        }
        if (lane == 0) { sh_p[0][w4] = pxy; sh_p[1][w4] = pxx; }
    }
    __syncthreads();

    if (tid < 64) {
        atomicAdd(&g_rs[0][I + tid], sh_rs[0][tid]);
        atomicAdd(&g_rs[1][I + tid], sh_rs[1][tid]);
        if (!diag) {
            atomicAdd(&g_rs[0][J + tid], sh_cs[0][tid]);
            atomicAdd(&g_rs[1][J + tid], sh_cs[1][tid]);
        }
    }
    if (tid == 0) {
        const double scl = diag ? 1.0 : 2.0;
        double s0 = 0, s1 = 0, s2 = 0;
#pragma unroll
        for (int q = 0; q < 4; ++q) { s0 += sh_p[0][q]; s1 += sh_p[1][q]; s2 += sh_p[2][q]; }
        atomicAdd(&g_acc[0], scl * s0);
        atomicAdd(&g_acc[1], scl * s1);
        atomicAdd(&g_acc[2], scl * s2);
    }

    // -------- last-block finalize (threadfence + ticket) --------
    __threadfence();
    __syncthreads();
    if (tid == 0) s_last = (atomicAdd(&g_ticket, 1u) == NBLK - 1) ? 1u : 0u;
    __syncthreads();
    if (s_last == 0u) return;
    __threadfence();

    double sRR = 0.0, sXX = 0.0, sYY = 0.0, sX = 0.0, sY = 0.0;
#pragma unroll
    for (int q = 0; q < 4; ++q) {
        const int i = tid + q * 256;
        const double rx = (double)g_rs[0][i];
        const double ry = (double)g_rs[1][i];
        sRR += rx * ry; sXX += rx * rx; sYY += ry * ry; sX += rx; sY += ry;
    }
#pragma unroll
    for (int off = 16; off > 0; off >>= 1) {
        sRR += __shfl_down_sync(0xffffffffu, sRR, off);
        sXX += __shfl_down_sync(0xffffffffu, sXX, off);
        sYY += __shfl_down_sync(0xffffffffu, sYY, off);
        sX  += __shfl_down_sync(0xffffffffu, sX, off);
        sY  += __shfl_down_sync(0xffffffffu, sY, off);
    }
    __shared__ double sd[5][8];
    if (lane == 0) { sd[0][warp] = sRR; sd[1][warp] = sXX; sd[2][warp] = sYY; sd[3][warp] = sX; sd[4][warp] = sY; }
    __syncthreads();
    if (tid == 0) {
        double a0 = 0, a1 = 0, a2 = 0, a3 = 0, a4 = 0;
#pragma unroll
        for (int q = 0; q < 8; ++q) {
            a0 += sd[0][q]; a1 += sd[1][q]; a2 += sd[2][q]; a3 += sd[3][q]; a4 += sd[4][q];
        }
        const double N = (double)NPTS, N2 = N * N;
        const double sumab = g_acc[0] - (2.0 / N) * a0 + (a3 * a4) / N2;
        const double sumaa = g_acc[1] - (2.0 / N) * a1 + (a3 * a3) / N2;
        const double sumbb = g_acc[2] - (2.0 / N) * a2 + (a4 * a4) / N2;
        const double mxy = sumab / N2, mxx = sumaa / N2, myy = sumbb / N2;
        const double r = mxy / sqrt(mxx * myy + 1e-9);
        out[0] = (float)(1.0 - r);
    }
}

extern "C" void kernel_launch(void* const* d_in, const int* in_sizes, int n_in,
                              void* d_out, int out_size) {
    const float* a = (const float*)d_in[0];  // output_1 (1024,64,256) f32
    const float* b = (const float*)d_in[1];  // feature  (1024,64,256) f32
    // d_in[2] = mask, unused by the reference module.

    mean_norm_kernel<<<dim3(NPTS / 2, 2), 256>>>(a, b);
    gemm_mma_kernel<<<NBLK, 256>>>((float*)d_out);
}